// round 16
// baseline (speedup 1.0000x reference)
#include <cuda_runtime.h>
#include <cuda_fp16.h>
#include <math.h>
#include <stdint.h>

#define T_   1024
#define HID_ 5120
#define NH_  128
#define DN_  128
#define DR_  64
#define DV_  128
#define QLR_ 1536
#define KVLR_ 512
#define DQK_ 192    // DN+DR
#define DKV_ 256    // DN+DV
#define NQKV_ 2112  // QLR+KVLR+DR
#define NQKV_PAD_ 2304

// ---------------- fp32 scratch ----------------------------------------------
__device__ float g_qkv [T_ * NQKV_];
__device__ float g_part[3][T_ * HID_];         // split-K partials for GEMM4
__device__ float g_cos [T_ * 32];
__device__ float g_sin [T_ * 32];

// ---------------- fp16 scratch ----------------------------------------------
__device__ __half g_w1[HID_ * NQKV_PAD_];
__device__ __half g_w2[QLR_ * (NH_*DQK_)];
__device__ __half g_w3[KVLR_ * (NH_*DKV_)];
__device__ __half g_w4[(NH_*DV_) * HID_];
__device__ __half g_a [T_ * (NH_*DV_)];
__device__ __half g_qan[T_ * QLR_];
__device__ __half g_kvan[T_ * KVLR_];
__device__ __half g_qh[T_ * NH_ * DQK_];
__device__ __half g_kh[T_ * NH_ * DQK_];
__device__ __half g_vh[T_ * NH_ * DV_];

// ======================= PTX helpers =========================================
__device__ __forceinline__ uint32_t smem_u32(const void* p) {
    uint32_t a;
    asm("{ .reg .u64 t; cvta.to.shared.u64 t, %1; cvt.u32.u64 %0, t; }" : "=r"(a) : "l"(p));
    return a;
}

#define CP_ASYNC16(dst_u32, src_ptr) \
    asm volatile("cp.async.cg.shared.global [%0], [%1], 16;" :: "r"(dst_u32), "l"(src_ptr))
#define CP_COMMIT() asm volatile("cp.async.commit_group;" ::: "memory")
#define CP_WAIT1()  asm volatile("cp.async.wait_group 1;" ::: "memory")
#define CP_WAIT0()  asm volatile("cp.async.wait_group 0;" ::: "memory")

#define LDSM_X4(r0, r1, r2, r3, addr) \
    asm volatile("ldmatrix.sync.aligned.m8n8.x4.shared.b16 {%0,%1,%2,%3}, [%4];" \
        : "=r"(r0), "=r"(r1), "=r"(r2), "=r"(r3) : "r"(addr))
#define LDSM_X2(r0, r1, addr) \
    asm volatile("ldmatrix.sync.aligned.m8n8.x2.shared.b16 {%0,%1}, [%2];" \
        : "=r"(r0), "=r"(r1) : "r"(addr))
#define LDSM_X4T(r0, r1, r2, r3, addr) \
    asm volatile("ldmatrix.sync.aligned.m8n8.x4.trans.shared.b16 {%0,%1,%2,%3}, [%4];" \
        : "=r"(r0), "=r"(r1), "=r"(r2), "=r"(r3) : "r"(addr))

#define MMA16816(d, a, b) \
    asm volatile("mma.sync.aligned.m16n8k16.row.col.f32.f16.f16.f32 " \
        "{%0,%1,%2,%3},{%4,%5,%6,%7},{%8,%9},{%0,%1,%2,%3};" \
        : "+f"((d)[0]), "+f"((d)[1]), "+f"((d)[2]), "+f"((d)[3]) \
        : "r"((a)[0]), "r"((a)[1]), "r"((a)[2]), "r"((a)[3]), "r"((b)[0]), "r"((b)[1]))

// ======================= fp16 conversion =====================================
__device__ __forceinline__ uint32_t pack2h(__half a, __half b) {
    __half2 t(a, b);
    return *(uint32_t*)&t;
}

__global__ void zero_qkv_kernel() {
    const int i = blockIdx.x * blockDim.x + threadIdx.x;
    if (i < T_ * NQKV_ / 4) ((float4*)g_qkv)[i] = make_float4(0.f, 0.f, 0.f, 0.f);
}

// zero out + 3 partial buffers
__global__ void zero_out4_kernel(float* __restrict__ out, int n4) {
    const int i = blockIdx.x * blockDim.x + threadIdx.x;
    if (i < n4) {
        const float4 z = make_float4(0.f, 0.f, 0.f, 0.f);
        ((float4*)out)[i] = z;
        ((float4*)g_part[0])[i] = z;
        ((float4*)g_part[1])[i] = z;
        ((float4*)g_part[2])[i] = z;
    }
}

// out += p0 + p1 + p2 (fixed order, deterministic)
__global__ void addpart3_kernel(float* __restrict__ out, int n4) {
    const int i = blockIdx.x * blockDim.x + threadIdx.x;
    if (i < n4) {
        float4 o = ((float4*)out)[i];
        const float4 a = ((const float4*)g_part[0])[i];
        const float4 b = ((const float4*)g_part[1])[i];
        const float4 c = ((const float4*)g_part[2])[i];
        o.x = ((o.x + a.x) + b.x) + c.x;
        o.y = ((o.y + a.y) + b.y) + c.y;
        o.z = ((o.z + a.z) + b.z) + c.z;
        o.w = ((o.w + a.w) + b.w) + c.w;
        ((float4*)out)[i] = o;
    }
}

__global__ void convA8_kernel(const float* __restrict__ A,
                              __half* __restrict__ H, int n8) {
    int i = blockIdx.x * blockDim.x + threadIdx.x;
    if (i < n8) {
        const float4* s = (const float4*)A + (size_t)i * 2;
        const float4 v0 = s[0], v1 = s[1];
        uint4 o;
        o.x = pack2h(__float2half_rn(v0.x), __float2half_rn(v0.y));
        o.y = pack2h(__float2half_rn(v0.z), __float2half_rn(v0.w));
        o.z = pack2h(__float2half_rn(v1.x), __float2half_rn(v1.y));
        o.w = pack2h(__float2half_rn(v1.z), __float2half_rn(v1.w));
        ((uint4*)H)[i] = o;
    }
}

__global__ void convH16_kernel(const float* __restrict__ A,
                               __half* __restrict__ O, int n16) {
    int i = blockIdx.x * blockDim.x + threadIdx.x;
    if (i >= n16) return;
    const float4* s = (const float4*)A + (size_t)i * 4;
    const float4 v0 = s[0], v1 = s[1], v2 = s[2], v3 = s[3];
    uint4 o0, o1;
    o0.x = pack2h(__float2half_rn(v0.x), __float2half_rn(v0.y));
    o0.y = pack2h(__float2half_rn(v0.z), __float2half_rn(v0.w));
    o0.z = pack2h(__float2half_rn(v1.x), __float2half_rn(v1.y));
    o0.w = pack2h(__float2half_rn(v1.z), __float2half_rn(v1.w));
    o1.x = pack2h(__float2half_rn(v2.x), __float2half_rn(v2.y));
    o1.y = pack2h(__float2half_rn(v2.z), __float2half_rn(v2.w));
    o1.z = pack2h(__float2half_rn(v3.x), __float2half_rn(v3.y));
    o1.w = pack2h(__float2half_rn(v3.z), __float2half_rn(v3.w));
    uint4* d = (uint4*)O + (size_t)i * 2;
    d[0] = o0; d[1] = o1;
}

__global__ void convHpad_kernel(const float* __restrict__ B, __half* __restrict__ O,
                                int N, int Npad, int total8) {
    int i = blockIdx.x * blockDim.x + threadIdx.x;
    if (i >= total8) return;
    const int npad8 = Npad >> 3;
    const int row = i / npad8;
    const int n8 = (i - row * npad8) << 3;
    uint4 o;
    if (n8 + 8 <= N) {
        const float4 v0 = *(const float4*)(B + (size_t)row * N + n8);
        const float4 v1 = *(const float4*)(B + (size_t)row * N + n8 + 4);
        o.x = pack2h(__float2half_rn(v0.x), __float2half_rn(v0.y));
        o.y = pack2h(__float2half_rn(v0.z), __float2half_rn(v0.w));
        o.z = pack2h(__float2half_rn(v1.x), __float2half_rn(v1.y));
        o.w = pack2h(__float2half_rn(v1.z), __float2half_rn(v1.w));
    } else {
        __half t[8];
#pragma unroll
        for (int j = 0; j < 8; j++)
            t[j] = (n8 + j < N) ? __float2half_rn(B[(size_t)row * N + n8 + j]) : __half(0.f);
        o.x = pack2h(t[0], t[1]); o.y = pack2h(t[2], t[3]);
        o.z = pack2h(t[4], t[5]); o.w = pack2h(t[6], t[7]);
    }
    *(uint4*)(O + ((size_t)i << 3)) = o;
}

// ======================= fp16 HMMA GEMM body =================================
// 8 warps, 128x128 CTA tile, BK=64, 3-stage single-sync pipeline, 256 threads.
#define APITCH 144
#define ATILE  (128 * APITCH)
#define BPITCH 272
#define BTILE  (64 * BPITCH)
#define GSTAGE (ATILE + BTILE)
#define GEMM_SMEM (3 * GSTAGE)

__device__ __forceinline__ void gemm_body(
        const __half* __restrict__ A, const __half* __restrict__ Bw,
        float* __restrict__ Ct, int Nreal, int ldC, int K, int ldB, int mode,
        __half* __restrict__ outH, __half* __restrict__ voutH,
        int bm, int bn, int kbase, int Kpart, int doAtomic, char* smem) {
    const uint32_t sb = smem_u32(smem);
    const int tid  = threadIdx.x;
    const int wid  = tid >> 5;
    const int lane = tid & 31;
    const int wm   = wid & 1;
    const int wn   = wid >> 1;
    const int nchunks = Kpart >> 6;

    auto issue = [&](int stage, int c) {
        const int k0 = kbase + (c << 6);
        const uint32_t st = sb + stage * GSTAGE;
        {
            const int rbase = tid >> 3, c8 = tid & 7;
#pragma unroll
            for (int p = 0; p < 4; p++) {
                const int row = rbase + p * 32;
                CP_ASYNC16(st + row * APITCH + c8 * 16,
                           A + (size_t)(bm + row) * K + k0 + c8 * 8);
            }
        }
        {
            const int rbase = tid >> 4, c16 = tid & 15;
#pragma unroll
            for (int p = 0; p < 4; p++) {
                const int row = rbase + p * 16;
                CP_ASYNC16(st + ATILE + row * BPITCH + c16 * 16,
                           Bw + (size_t)(k0 + row) * ldB + bn + c16 * 8);
            }
        }
    };

    float acc[4][4][4];
#pragma unroll
    for (int i = 0; i < 4; i++)
#pragma unroll
        for (int j = 0; j < 4; j++)
#pragma unroll
            for (int q = 0; q < 4; q++) acc[i][j][q] = 0.f;

    uint32_t aoff[4], boffT[2];
#pragma unroll
    for (int mf = 0; mf < 4; mf++) {
        const int row = wm * 64 + mf * 16 + (lane & 15);
        aoff[mf] = row * APITCH + ((lane >> 4) & 1) * 16;
    }
#pragma unroll
    for (int j = 0; j < 2; j++)
        boffT[j] = (lane & 15) * BPITCH + (wn * 32 + j * 16 + ((lane >> 4) & 1) * 8) * 2;

    issue(0, 0); CP_COMMIT();
    if (nchunks > 1) issue(1, 1);
    CP_COMMIT();

    const int ksrot = (wid & 1) << 1;   // stagger warp phases on the crossbar
    int stage = 0;
    for (int c = 0; c < nchunks; c++) {
        CP_WAIT1();
        __syncthreads();
        if (c + 2 < nchunks) {
            int s2 = stage + 2;
            if (s2 >= 3) s2 -= 3;
            issue(s2, c + 2);
        }
        CP_COMMIT();
        const uint32_t st = sb + stage * GSTAGE;
#pragma unroll
        for (int kk = 0; kk < 4; kk++) {
            const int ks = kk ^ ksrot;
            uint32_t a[4][4], b[4][2];
#pragma unroll
            for (int mf = 0; mf < 4; mf++)
                LDSM_X4(a[mf][0], a[mf][1], a[mf][2], a[mf][3],
                        st + aoff[mf] + ks * 32);
#pragma unroll
            for (int j = 0; j < 2; j++)
                LDSM_X4T(b[2*j][0], b[2*j][1], b[2*j+1][0], b[2*j+1][1],
                         st + ATILE + boffT[j] + ks * (16 * BPITCH));
#pragma unroll
            for (int mf = 0; mf < 4; mf++)
#pragma unroll
                for (int nf = 0; nf < 4; nf++)
                    MMA16816(acc[mf][nf], a[mf], b[nf]);
        }
        stage = (stage == 2) ? 0 : stage + 1;
    }

    const int lm = lane >> 2, ln = (lane & 3) * 2;
    const float qscale = 0.072168784f; // 1/sqrt(192)
#pragma unroll
    for (int mf = 0; mf < 4; mf++) {
#pragma unroll
        for (int nf = 0; nf < 4; nf++) {
            const int n = bn + wn * 32 + nf * 8 + ln;
            const int m = bm + wm * 64 + mf * 16 + lm;
            if (mode == 0) {
                if (n < Nreal) {
                    float* p0 = Ct + (size_t)m * ldC + n;
                    float* p1 = Ct + (size_t)(m + 8) * ldC + n;
                    if (doAtomic) {
                        atomicAdd(p0 + 0, acc[mf][nf][0]);
                        atomicAdd(p0 + 1, acc[mf][nf][1]);
                        atomicAdd(p1 + 0, acc[mf][nf][2]);
                        atomicAdd(p1 + 1, acc[mf][nf][3]);
                    } else {
                        p0[0] = acc[mf][nf][0]; p0[1] = acc[mf][nf][1];
                        p1[0] = acc[mf][nf][2]; p1[1] = acc[mf][nf][3];
                    }
                }
            } else if (mode == 1) {
                const int d = n % DQK_;
#pragma unroll
                for (int rr = 0; rr < 2; rr++) {
                    const int mr = m + rr * 8;
                    float x1 = acc[mf][nf][rr * 2 + 0] * qscale;
                    float x2 = acc[mf][nf][rr * 2 + 1] * qscale;
                    if (d >= DN_) {
                        const int j = (d - DN_) >> 1;
                        const float cc = g_cos[mr * 32 + j], ss = g_sin[mr * 32 + j];
                        const float o1 = x1 * cc - x2 * ss, o2 = x2 * cc + x1 * ss;
                        x1 = o1; x2 = o2;
                    }
                    *(uint32_t*)(outH + (size_t)mr * ldC + n) =
                        pack2h(__float2half_rn(x1), __float2half_rn(x2));
                }
            } else { // mode 2
                const int d = n & 255, hh = n >> 8;
#pragma unroll
                for (int rr = 0; rr < 2; rr++) {
                    const int mr = m + rr * 8;
                    const float x1 = acc[mf][nf][rr * 2 + 0];
                    const float x2 = acc[mf][nf][rr * 2 + 1];
                    if (d < DN_) {
                        *(uint32_t*)(outH + ((size_t)mr * NH_ + hh) * DQK_ + d) =
                            pack2h(__float2half_rn(x1), __float2half_rn(x2));
                    } else {
                        *(uint32_t*)(voutH + ((size_t)mr * NH_ + hh) * DV_ + (d - DN_)) =
                            pack2h(__float2half_rn(x1), __float2half_rn(x2));
                    }
                }
            }
        }
    }
}

// mode-0 GEMM with split-K via gridDim.z; z-pairs route to distinct buffers
// (2 commutative atomic addends per buffer -> deterministic).
__global__ void __launch_bounds__(256, 2)
gemm_hmma(const __half* __restrict__ A, const __half* __restrict__ Bw,
          float* __restrict__ C, int Nreal, int ldC, int K, int ldB) {
    extern __shared__ char smem[];
    const int nsplit = gridDim.z;
    const int Kpart = K / nsplit;
    const int kbase = blockIdx.z * Kpart;
    float* Ct = C;
    const int g = blockIdx.z >> 1;
    if (g > 0) Ct = &g_part[g - 1][0];
    gemm_body(A, Bw, Ct, Nreal, ldC, K, ldB, 0, nullptr, nullptr,
              blockIdx.y * 128, blockIdx.x * 128, kbase, Kpart,
              nsplit > 1 ? 1 : 0, smem);
}

// fused GEMM2 (mode 1) + GEMM3 (mode 2) in one grid; GEMM2 tiles first.
#define G2_CTAS (((NH_*DQK_) / 128) * (T_ / 128))   // 192*8 = 1536
#define G3_CTAS (((NH_*DKV_) / 128) * (T_ / 128))   // 256*8 = 2048
__global__ void __launch_bounds__(256, 2)
gemm23_fused() {
    extern __shared__ char smem[];
    int id = blockIdx.x;
    const __half* A; const __half* Bw; __half* oH; __half* vH;
    int mode, Nn, K, bm, bn;
    if (id < G2_CTAS) {
        const int bx = id % ((NH_*DQK_) / 128), by = id / ((NH_*DQK_) / 128);
        A = g_qan; Bw = g_w2; oH = g_qh; vH = nullptr;
        mode = 1; Nn = NH_ * DQK_; K = QLR_;
        bm = by * 128; bn = bx * 128;
    } else {
        id -= G2_CTAS;
        const int bx = id % ((NH_*DKV_) / 128), by = id / ((NH_*DKV_) / 128);
        A = g_kvan; Bw = g_w3; oH = g_kh; vH = g_vh;
        mode = 2; Nn = NH_ * DKV_; K = KVLR_;
        bm = by * 128; bn = bx * 128;
    }
    gemm_body(A, Bw, nullptr, Nn, Nn, K, Nn, mode, oH, vH,
              bm, bn, 0, K, 0, smem);
}

// ======================= rmsnorm (both in one launch) ========================
__global__ void rmsnorm2_kernel(const float* __restrict__ qw,
                                const float* __restrict__ kvw) {
    const int row = blockIdx.x;
    const int which = blockIdx.y;
    const int W = which ? KVLR_ : QLR_;
    const int off = which ? QLR_ : 0;
    const float* w = which ? kvw : qw;
    __half* H = which ? g_kvan : g_qan;
    const float* xr = g_qkv + (size_t)row * NQKV_ + off;
    float ss = 0.f;
    for (int c = threadIdx.x; c < W; c += blockDim.x) {
        float v = xr[c];
        ss += v * v;
    }
    __shared__ float red[32];
#pragma unroll
    for (int o = 16; o; o >>= 1) ss += __shfl_xor_sync(0xffffffffu, ss, o);
    if ((threadIdx.x & 31) == 0) red[threadIdx.x >> 5] = ss;
    __syncthreads();
    if (threadIdx.x < 32) {
        float v = (threadIdx.x < (blockDim.x >> 5)) ? red[threadIdx.x] : 0.f;
#pragma unroll
        for (int o = 16; o; o >>= 1) v += __shfl_xor_sync(0xffffffffu, v, o);
        red[threadIdx.x] = v;
    }
    __syncthreads();
    const float rstd = rsqrtf(red[0] / (float)W + 1e-6f);
    for (int c = threadIdx.x; c < W; c += blockDim.x)
        H[(size_t)row * W + c] = __float2half_rn(xr[c] * rstd * w[c]);
}

// ======================= RoPE tables + k_pe broadcast ========================
__global__ void rope_tab_kernel(const int* __restrict__ pos) {
    const int t = blockIdx.x, i = threadIdx.x;
    double inv = pow(10000.0, -(double)i / 32.0);
    double f = (double)pos[t] * inv;
    double s, c;
    sincos(f, &s, &c);
    g_cos[t * 32 + i] = (float)c;
    g_sin[t * 32 + i] = (float)s;
}

__global__ void kpe_build_kernel() {
    const int t = blockIdx.x;
    const int i = threadIdx.x;
    const int hh = threadIdx.y;
    const float c = g_cos[t * 32 + i];
    const float s = g_sin[t * 32 + i];
    const float* src = g_qkv + (size_t)t * NQKV_ + (QLR_ + KVLR_) + 2 * i;
    const float x1 = src[0], x2 = src[1];
    const uint32_t hv = pack2h(__float2half_rn(x1 * c - x2 * s),
                               __float2half_rn(x2 * c + x1 * s));
    for (int h = hh; h < NH_; h += 8)
        *(uint32_t*)(g_kh + ((size_t)t * NH_ + h) * DQK_ + DN_ + 2 * i) = hv;
}

// ======================= fp16 HMMA flash attention ===========================
#define QKP 200
#define VPITCH 272
#define PVP 72
#define SFP 68

struct ASmem {
    __half Q[64 * QKP];
    __half K[64 * QKP];
    char  V[64 * VPITCH];
    __half P[64 * PVP];
    float Sf[64 * SFP];
    float rowM[64], rowL[64], rowScale[64];
};
#define ATTN_SMEM sizeof(ASmem)

__global__ void __launch_bounds__(256, 2)
attn_mma() {
    extern __shared__ char smem_raw[];
    ASmem& sm = *(ASmem*)smem_raw;
    const int h = blockIdx.x;
    const int qb = (int)gridDim.y - 1 - (int)blockIdx.y;  // long tiles first
    const int tid = threadIdx.x, wid = tid >> 5, lane = tid & 31;
    const int wm = wid & 3, wn = wid >> 2;
    const int t0 = qb * 64;
    const int lm = lane >> 2, ln = (lane & 3) * 2;

    const uint32_t sQ = smem_u32(sm.Q);
    const uint32_t sK = smem_u32(sm.K);
    const uint32_t sV = smem_u32(sm.V);
    const uint32_t sP = smem_u32(sm.P);

    auto loadK = [&](int kc) {
        const int tk0 = kc * 64;
        for (int idx = tid; idx < 64 * 24; idx += 256) {
            const int row = idx / 24, ch = idx % 24;
            CP_ASYNC16(sK + (row * QKP + ch * 8) * 2,
                       g_kh + ((size_t)(tk0 + row) * NH_ + h) * DQK_ + ch * 8);
        }
    };
    auto loadV = [&](int kc) {
        const int tk0 = kc * 64;
        for (int idx = tid; idx < 64 * 16; idx += 256) {
            const int row = idx >> 4, ch = idx & 15;
            CP_ASYNC16(sV + row * VPITCH + ch * 16,
                       g_vh + ((size_t)(tk0 + row) * NH_ + h) * DV_ + ch * 8);
        }
    };

    for (int idx = tid; idx < 64 * 24; idx += 256) {
        const int row = idx / 24, ch = idx % 24;
        CP_ASYNC16(sQ + (row * QKP + ch * 8) * 2,
                   g_qh + ((size_t)(t0 + row) * NH_ + h) * DQK_ + ch * 8);
    }
    CP_COMMIT();
    loadK(0); CP_COMMIT();
    loadV(0); CP_COMMIT();

    if (tid < 64) {
        sm.rowM[tid] = -1e30f;
        sm.rowL[tid] = 0.f;
    }

    const uint32_t aoffQ = ((wm * 16 + (lane & 15)) * QKP + ((lane >> 4) & 1) * 8) * 2;
    uint32_t boffK[4];
#pragma unroll
    for (int nf = 0; nf < 4; nf++)
        boffK[nf] = ((wn * 32 + nf * 8 + (lane & 7)) * QKP + ((lane >> 3) & 1) * 8) * 2;
    const uint32_t aoffP = ((wm * 16 + (lane & 15)) * PVP + ((lane >> 4) & 1) * 8) * 2;
    uint32_t voffT[4];
#pragma unroll
    for (int j = 0; j < 4; j++)
        voffT[j] = (lane & 15) * VPITCH + (wn * 64 + j * 16 + ((lane >> 4) & 1) * 8) * 2;

    float accO[8][4];
#pragma unroll
    for (int i = 0; i < 8; i++)
#pragma unroll
        for (int q = 0; q < 4; q++) accO[i][q] = 0.f;

    for (int kc = 0; kc <= qb; kc++) {
        const int tk0 = kc * 64;
        CP_WAIT1();
        __syncthreads();

        float accS[4][4];
#pragma unroll
        for (int i = 0; i < 4; i++)
#pragma unroll
            for (int q = 0; q < 4; q++) accS[i][q] = 0.f;
#pragma unroll
        for (int ks = 0; ks < 12; ks++) {
            uint32_t a[4];
            LDSM_X4(a[0], a[1], a[2], a[3], sQ + aoffQ + ks * 32);
#pragma unroll
            for (int nf = 0; nf < 4; nf++) {
                uint32_t b[2];
                LDSM_X2(b[0], b[1], sK + boffK[nf] + ks * 32);
                MMA16816(accS[nf], a, b);
            }
        }
        const bool diag = (kc == qb);
#pragma unroll
        for (int nf = 0; nf < 4; nf++) {
            const int r = wm * 16 + lm;
            const int c = wn * 32 + nf * 8 + ln;
            float v0 = accS[nf][0], v1 = accS[nf][1], v2 = accS[nf][2], v3 = accS[nf][3];
            if (diag) {
                const int rg0 = t0 + r, rg1 = rg0 + 8, cg = tk0 + c;
                if (cg > rg0) v0 = -1e30f;
                if (cg + 1 > rg0) v1 = -1e30f;
                if (cg > rg1) v2 = -1e30f;
                if (cg + 1 > rg1) v3 = -1e30f;
            }
            sm.Sf[r * SFP + c] = v0;
            sm.Sf[r * SFP + c + 1] = v1;
            sm.Sf[(r + 8) * SFP + c] = v2;
            sm.Sf[(r + 8) * SFP + c + 1] = v3;
        }
        __syncthreads();

        if (kc < qb) { loadK(kc + 1); CP_COMMIT(); }

        {
            const int row = tid >> 2, l4 = tid & 3;
            float mloc = -1e30f;
#pragma unroll
            for (int c = 0; c < 16; c++) mloc = fmaxf(mloc, sm.Sf[row * SFP + l4 * 16 + c]);
            mloc = fmaxf(mloc, __shfl_xor_sync(0xffffffffu, mloc, 1));
            mloc = fmaxf(mloc, __shfl_xor_sync(0xffffffffu, mloc, 2));
            const float mprev = sm.rowM[row];
            const float mnew = fmaxf(mprev, mloc);
            float lsum = 0.f;
#pragma unroll
            for (int c = 0; c < 16; c += 2) {
                const int col = l4 * 16 + c;
                const float p0 = __expf(sm.Sf[row * SFP + col] - mnew);
                const float p1 = __expf(sm.Sf[row * SFP + col + 1] - mnew);
                lsum += p0 + p1;
                *(uint32_t*)(sm.P + row * PVP + col) =
                    pack2h(__float2half_rn(p0), __float2half_rn(p1));
            }
            lsum += __shfl_xor_sync(0xffffffffu, lsum, 1);
            lsum += __shfl_xor_sync(0xffffffffu, lsum, 2);
            if (l4 == 0) {
                const float sc = __expf(mprev - mnew);
                sm.rowScale[row] = sc;
                sm.rowM[row] = mnew;
                sm.rowL[row] = sm.rowL[row] * sc + lsum;
            }
        }

        if (kc < qb) { CP_WAIT1(); } else { CP_WAIT0(); }
        __syncthreads();

        const float s0 = sm.rowScale[wm * 16 + lm];
        const float s1 = sm.rowScale[wm * 16 + lm + 8];
#pragma unroll
        for (int nf = 0; nf < 8; nf++) {
            accO[nf][0] *= s0; accO[nf][1] *= s0;
            accO[nf][2] *= s1; accO[nf][3] *= s1;
        }
#pragma unroll
        for (int ks = 0; ks < 4; ks++) {
            uint32_t pa[4];
            LDSM_X4(pa[0], pa[1], pa[2], pa[3], sP + aoffP + ks * 32);
#pragma unroll
            for (int j = 0; j < 4; j++) {
                uint32_t vb[4];
                LDSM_X4T(vb[0], vb[1], vb[2], vb[3],
                         sV + voffT[j] + ks * (16 * VPITCH));
                MMA16816(accO[2*j],     pa, vb);
                MMA16816(accO[2*j + 1], pa, vb + 2);
            }
        }
        __syncthreads();

        if (kc < qb) { loadV(kc + 1); CP_COMMIT(); }
    }

    const float invL0 = 1.f / sm.rowL[wm * 16 + lm];
    const float invL1 = 1.f / sm.rowL[wm * 16 + lm + 8];
    const int r0g = t0 + wm * 16 + lm;
#pragma unroll
    for (int nf = 0; nf < 8; nf++) {
        const int col = h * DV_ + wn * 64 + nf * 8 + ln;
        *(uint32_t*)(g_a + (size_t)r0g * (NH_ * DV_) + col) =
            pack2h(__float2half_rn(accO[nf][0] * invL0), __float2half_rn(accO[nf][1] * invL0));
        *(uint32_t*)(g_a + (size_t)(r0g + 8) * (NH_ * DV_) + col) =
            pack2h(__float2half_rn(accO[nf][2] * invL1), __float2half_rn(accO[nf][3] * invL1));
    }
}

// ======================= launch ==============================================
extern "C" void kernel_launch(void* const* d_in, const int* in_sizes, int n_in,
                              void* d_out, int out_size) {
    const int*   positions = (const int*)d_in[0];
    const float* hidden    = (const float*)d_in[1];
    const float* w_qkv_a   = (const float*)d_in[2];
    const float* q_a_ln_w  = (const float*)d_in[3];
    const float* w_q_b     = (const float*)d_in[4];
    const float* kv_a_ln_w = (const float*)d_in[5];
    const float* w_kv_b    = (const float*)d_in[6];
    const float* w_o       = (const float*)d_in[7];
    float* out = (float*)d_out;

    float* p_qkv;
    cudaGetSymbolAddress((void**)&p_qkv, g_qkv);

    __half *w1, *w2, *w3, *w4, *a;
    cudaGetSymbolAddress((void**)&w1, g_w1);
    cudaGetSymbolAddress((void**)&w2, g_w2);
    cudaGetSymbolAddress((void**)&w3, g_w3);
    cudaGetSymbolAddress((void**)&w4, g_w4);
    cudaGetSymbolAddress((void**)&a,  g_a);

    cudaFuncSetAttribute(gemm_hmma, cudaFuncAttributeMaxDynamicSharedMemorySize, GEMM_SMEM);
    cudaFuncSetAttribute(gemm23_fused, cudaFuncAttributeMaxDynamicSharedMemorySize, GEMM_SMEM);
    cudaFuncSetAttribute(attn_mma, cudaFuncAttributeMaxDynamicSharedMemorySize, (int)ATTN_SMEM);

    // keep gemm_hmma (GEMM1) as the 4th launch for ncu capture
    zero_qkv_kernel<<<(T_ * NQKV_ / 4 + 255) / 256, 256>>>();
    {
        int t8 = HID_ * NQKV_PAD_ / 8;
        convHpad_kernel<<<(t8 + 255) / 256, 256>>>(w_qkv_a, w1, NQKV_, NQKV_PAD_, t8);
    }
    convA8_kernel<<<(T_ * HID_ / 8 + 255) / 256, 256>>>(hidden, a, T_ * HID_ / 8);
    // GEMM1 split-K=2 (both z into g_qkv; 2 commutative addends)
    gemm_hmma<<<dim3(NQKV_PAD_ / 128, T_ / 128, 2), 256, GEMM_SMEM>>>(
        a, w1, p_qkv, NQKV_, NQKV_, HID_, NQKV_PAD_);

    {
        int t16;
        t16 = QLR_ * (NH_ * DQK_) / 16;
        convH16_kernel<<<(t16 + 255) / 256, 256>>>(w_q_b, w2, t16);
        t16 = KVLR_ * (NH_ * DKV_) / 16;
        convH16_kernel<<<(t16 + 255) / 256, 256>>>(w_kv_b, w3, t16);
        t16 = (NH_ * DV_) * HID_ / 16;
        convH16_kernel<<<(t16 + 255) / 256, 256>>>(w_o, w4, t16);
    }

    // zero d_out + 3 partial buffers (GEMM4 split-K=8 targets)
    zero_out4_kernel<<<(T_ * HID_ / 4 + 255) / 256, 256>>>(out, T_ * HID_ / 4);

    rope_tab_kernel<<<T_, 32>>>(positions);
    rmsnorm2_kernel<<<dim3(T_, 2), 256>>>(q_a_ln_w, kv_a_ln_w);

    // fused GEMM2+GEMM3 (one grid, GEMM2 tiles first)
    gemm23_fused<<<G2_CTAS + G3_CTAS, 256, GEMM_SMEM>>>();

    kpe_build_kernel<<<T_, dim3(32, 8)>>>();

    attn_mma<<<dim3(NH_, T_ / 64), 256, ATTN_SMEM>>>();

    // GEMM4 split-K=8: z-pairs -> {out, part0, part1, part2}, 2 addends each
    gemm_hmma<<<dim3(HID_ / 128, T_ / 128, 8), 256, GEMM_SMEM>>>(
        a, w4, out, HID_, HID_, NH_ * DV_, HID_);
    addpart3_kernel<<<(T_ * HID_ / 4 + 255) / 256, 256>>>(out, T_ * HID_ / 4);
}

// round 17
// speedup vs baseline: 1.0264x; 1.0264x over previous
#include <cuda_runtime.h>
#include <cuda_fp16.h>
#include <math.h>
#include <stdint.h>

#define T_   1024
#define HID_ 5120
#define NH_  128
#define DN_  128
#define DR_  64
#define DV_  128
#define QLR_ 1536
#define KVLR_ 512
#define DQK_ 192    // DN+DR
#define DKV_ 256    // DN+DV
#define NQKV_ 2112  // QLR+KVLR+DR
#define NQKV_PAD_ 2304

// ---------------- fp32 scratch ----------------------------------------------
__device__ float g_qkv [T_ * NQKV_];
__device__ float g_part[3][T_ * HID_];         // split-K partials for GEMM4
__device__ float g_cos [T_ * 32];
__device__ float g_sin [T_ * 32];

// ---------------- fp16 scratch ----------------------------------------------
__device__ __half g_w1[HID_ * NQKV_PAD_];
__device__ __half g_w2[QLR_ * (NH_*DQK_)];
__device__ __half g_w3[KVLR_ * (NH_*DKV_)];
__device__ __half g_w4[(NH_*DV_) * HID_];
__device__ __half g_a [T_ * (NH_*DV_)];
__device__ __half g_qan[T_ * QLR_];
__device__ __half g_kvan[T_ * KVLR_];
__device__ __half g_qh[T_ * NH_ * DQK_];
__device__ __half g_kh[T_ * NH_ * DQK_];
__device__ __half g_vh[T_ * NH_ * DV_];

// ======================= PTX helpers =========================================
__device__ __forceinline__ uint32_t smem_u32(const void* p) {
    uint32_t a;
    asm("{ .reg .u64 t; cvta.to.shared.u64 t, %1; cvt.u32.u64 %0, t; }" : "=r"(a) : "l"(p));
    return a;
}

#define CP_ASYNC16(dst_u32, src_ptr) \
    asm volatile("cp.async.cg.shared.global [%0], [%1], 16;" :: "r"(dst_u32), "l"(src_ptr))
#define CP_COMMIT() asm volatile("cp.async.commit_group;" ::: "memory")
#define CP_WAIT1()  asm volatile("cp.async.wait_group 1;" ::: "memory")
#define CP_WAIT0()  asm volatile("cp.async.wait_group 0;" ::: "memory")

#define LDSM_X4(r0, r1, r2, r3, addr) \
    asm volatile("ldmatrix.sync.aligned.m8n8.x4.shared.b16 {%0,%1,%2,%3}, [%4];" \
        : "=r"(r0), "=r"(r1), "=r"(r2), "=r"(r3) : "r"(addr))
#define LDSM_X2(r0, r1, addr) \
    asm volatile("ldmatrix.sync.aligned.m8n8.x2.shared.b16 {%0,%1}, [%2];" \
        : "=r"(r0), "=r"(r1) : "r"(addr))
#define LDSM_X4T(r0, r1, r2, r3, addr) \
    asm volatile("ldmatrix.sync.aligned.m8n8.x4.trans.shared.b16 {%0,%1,%2,%3}, [%4];" \
        : "=r"(r0), "=r"(r1), "=r"(r2), "=r"(r3) : "r"(addr))

#define MMA16816(d, a, b) \
    asm volatile("mma.sync.aligned.m16n8k16.row.col.f32.f16.f16.f32 " \
        "{%0,%1,%2,%3},{%4,%5,%6,%7},{%8,%9},{%0,%1,%2,%3};" \
        : "+f"((d)[0]), "+f"((d)[1]), "+f"((d)[2]), "+f"((d)[3]) \
        : "r"((a)[0]), "r"((a)[1]), "r"((a)[2]), "r"((a)[3]), "r"((b)[0]), "r"((b)[1]))

// ======================= fp16 conversion =====================================
__device__ __forceinline__ uint32_t pack2h(__half a, __half b) {
    __half2 t(a, b);
    return *(uint32_t*)&t;
}

__global__ void zero_qkv_kernel() {
    const int i = blockIdx.x * blockDim.x + threadIdx.x;
    if (i < T_ * NQKV_ / 4) ((float4*)g_qkv)[i] = make_float4(0.f, 0.f, 0.f, 0.f);
}

// zero out + 3 partial buffers
__global__ void zero_out4_kernel(float* __restrict__ out, int n4) {
    const int i = blockIdx.x * blockDim.x + threadIdx.x;
    if (i < n4) {
        const float4 z = make_float4(0.f, 0.f, 0.f, 0.f);
        ((float4*)out)[i] = z;
        ((float4*)g_part[0])[i] = z;
        ((float4*)g_part[1])[i] = z;
        ((float4*)g_part[2])[i] = z;
    }
}

// out += p0 + p1 + p2 (fixed order, deterministic)
__global__ void addpart3_kernel(float* __restrict__ out, int n4) {
    const int i = blockIdx.x * blockDim.x + threadIdx.x;
    if (i < n4) {
        float4 o = ((float4*)out)[i];
        const float4 a = ((const float4*)g_part[0])[i];
        const float4 b = ((const float4*)g_part[1])[i];
        const float4 c = ((const float4*)g_part[2])[i];
        o.x = ((o.x + a.x) + b.x) + c.x;
        o.y = ((o.y + a.y) + b.y) + c.y;
        o.z = ((o.z + a.z) + b.z) + c.z;
        o.w = ((o.w + a.w) + b.w) + c.w;
        ((float4*)out)[i] = o;
    }
}

__global__ void convA8_kernel(const float* __restrict__ A,
                              __half* __restrict__ H, int n8) {
    int i = blockIdx.x * blockDim.x + threadIdx.x;
    if (i < n8) {
        const float4* s = (const float4*)A + (size_t)i * 2;
        const float4 v0 = s[0], v1 = s[1];
        uint4 o;
        o.x = pack2h(__float2half_rn(v0.x), __float2half_rn(v0.y));
        o.y = pack2h(__float2half_rn(v0.z), __float2half_rn(v0.w));
        o.z = pack2h(__float2half_rn(v1.x), __float2half_rn(v1.y));
        o.w = pack2h(__float2half_rn(v1.z), __float2half_rn(v1.w));
        ((uint4*)H)[i] = o;
    }
}

__global__ void convH16_kernel(const float* __restrict__ A,
                               __half* __restrict__ O, int n16) {
    int i = blockIdx.x * blockDim.x + threadIdx.x;
    if (i >= n16) return;
    const float4* s = (const float4*)A + (size_t)i * 4;
    const float4 v0 = s[0], v1 = s[1], v2 = s[2], v3 = s[3];
    uint4 o0, o1;
    o0.x = pack2h(__float2half_rn(v0.x), __float2half_rn(v0.y));
    o0.y = pack2h(__float2half_rn(v0.z), __float2half_rn(v0.w));
    o0.z = pack2h(__float2half_rn(v1.x), __float2half_rn(v1.y));
    o0.w = pack2h(__float2half_rn(v1.z), __float2half_rn(v1.w));
    o1.x = pack2h(__float2half_rn(v2.x), __float2half_rn(v2.y));
    o1.y = pack2h(__float2half_rn(v2.z), __float2half_rn(v2.w));
    o1.z = pack2h(__float2half_rn(v3.x), __float2half_rn(v3.y));
    o1.w = pack2h(__float2half_rn(v3.z), __float2half_rn(v3.w));
    uint4* d = (uint4*)O + (size_t)i * 2;
    d[0] = o0; d[1] = o1;
}

__global__ void convHpad_kernel(const float* __restrict__ B, __half* __restrict__ O,
                                int N, int Npad, int total8) {
    int i = blockIdx.x * blockDim.x + threadIdx.x;
    if (i >= total8) return;
    const int npad8 = Npad >> 3;
    const int row = i / npad8;
    const int n8 = (i - row * npad8) << 3;
    uint4 o;
    if (n8 + 8 <= N) {
        const float4 v0 = *(const float4*)(B + (size_t)row * N + n8);
        const float4 v1 = *(const float4*)(B + (size_t)row * N + n8 + 4);
        o.x = pack2h(__float2half_rn(v0.x), __float2half_rn(v0.y));
        o.y = pack2h(__float2half_rn(v0.z), __float2half_rn(v0.w));
        o.z = pack2h(__float2half_rn(v1.x), __float2half_rn(v1.y));
        o.w = pack2h(__float2half_rn(v1.z), __float2half_rn(v1.w));
    } else {
        __half t[8];
#pragma unroll
        for (int j = 0; j < 8; j++)
            t[j] = (n8 + j < N) ? __float2half_rn(B[(size_t)row * N + n8 + j]) : __half(0.f);
        o.x = pack2h(t[0], t[1]); o.y = pack2h(t[2], t[3]);
        o.z = pack2h(t[4], t[5]); o.w = pack2h(t[6], t[7]);
    }
    *(uint4*)(O + ((size_t)i << 3)) = o;
}

// ======================= fp16 HMMA GEMM body =================================
// 8 warps, 128x128 CTA tile, BK=64, 3-stage single-sync pipeline, 256 threads.
#define APITCH 144
#define ATILE  (128 * APITCH)
#define BPITCH 272
#define BTILE  (64 * BPITCH)
#define GSTAGE (ATILE + BTILE)
#define GEMM_SMEM (3 * GSTAGE)

__device__ __forceinline__ void gemm_body(
        const __half* __restrict__ A, const __half* __restrict__ Bw,
        float* __restrict__ Ct, int Nreal, int ldC, int K, int ldB, int mode,
        __half* __restrict__ outH, __half* __restrict__ voutH,
        int bm, int bn, int kbase, int Kpart, int doAtomic, char* smem) {
    const uint32_t sb = smem_u32(smem);
    const int tid  = threadIdx.x;
    const int wid  = tid >> 5;
    const int lane = tid & 31;
    const int wm   = wid & 1;
    const int wn   = wid >> 1;
    const int nchunks = Kpart >> 6;

    auto issue = [&](int stage, int c) {
        const int k0 = kbase + (c << 6);
        const uint32_t st = sb + stage * GSTAGE;
        {
            const int rbase = tid >> 3, c8 = tid & 7;
#pragma unroll
            for (int p = 0; p < 4; p++) {
                const int row = rbase + p * 32;
                CP_ASYNC16(st + row * APITCH + c8 * 16,
                           A + (size_t)(bm + row) * K + k0 + c8 * 8);
            }
        }
        {
            const int rbase = tid >> 4, c16 = tid & 15;
#pragma unroll
            for (int p = 0; p < 4; p++) {
                const int row = rbase + p * 16;
                CP_ASYNC16(st + ATILE + row * BPITCH + c16 * 16,
                           Bw + (size_t)(k0 + row) * ldB + bn + c16 * 8);
            }
        }
    };

    float acc[4][4][4];
#pragma unroll
    for (int i = 0; i < 4; i++)
#pragma unroll
        for (int j = 0; j < 4; j++)
#pragma unroll
            for (int q = 0; q < 4; q++) acc[i][j][q] = 0.f;

    uint32_t aoff[4], boffT[2];
#pragma unroll
    for (int mf = 0; mf < 4; mf++) {
        const int row = wm * 64 + mf * 16 + (lane & 15);
        aoff[mf] = row * APITCH + ((lane >> 4) & 1) * 16;
    }
#pragma unroll
    for (int j = 0; j < 2; j++)
        boffT[j] = (lane & 15) * BPITCH + (wn * 32 + j * 16 + ((lane >> 4) & 1) * 8) * 2;

    issue(0, 0); CP_COMMIT();
    if (nchunks > 1) issue(1, 1);
    CP_COMMIT();

    int stage = 0;
    for (int c = 0; c < nchunks; c++) {
        CP_WAIT1();
        __syncthreads();
        if (c + 2 < nchunks) {
            int s2 = stage + 2;
            if (s2 >= 3) s2 -= 3;
            issue(s2, c + 2);
        }
        CP_COMMIT();
        const uint32_t st = sb + stage * GSTAGE;
#pragma unroll
        for (int ks = 0; ks < 4; ks++) {
            uint32_t a[4][4], b[4][2];
#pragma unroll
            for (int mf = 0; mf < 4; mf++)
                LDSM_X4(a[mf][0], a[mf][1], a[mf][2], a[mf][3],
                        st + aoff[mf] + ks * 32);
#pragma unroll
            for (int j = 0; j < 2; j++)
                LDSM_X4T(b[2*j][0], b[2*j][1], b[2*j+1][0], b[2*j+1][1],
                         st + ATILE + boffT[j] + ks * (16 * BPITCH));
#pragma unroll
            for (int mf = 0; mf < 4; mf++)
#pragma unroll
                for (int nf = 0; nf < 4; nf++)
                    MMA16816(acc[mf][nf], a[mf], b[nf]);
        }
        stage = (stage == 2) ? 0 : stage + 1;
    }

    const int lm = lane >> 2, ln = (lane & 3) * 2;
    const float qscale = 0.072168784f; // 1/sqrt(192)
#pragma unroll
    for (int mf = 0; mf < 4; mf++) {
#pragma unroll
        for (int nf = 0; nf < 4; nf++) {
            const int n = bn + wn * 32 + nf * 8 + ln;
            const int m = bm + wm * 64 + mf * 16 + lm;
            if (mode == 0) {
                if (n < Nreal) {
                    float* p0 = Ct + (size_t)m * ldC + n;
                    float* p1 = Ct + (size_t)(m + 8) * ldC + n;
                    if (doAtomic) {
                        atomicAdd(p0 + 0, acc[mf][nf][0]);
                        atomicAdd(p0 + 1, acc[mf][nf][1]);
                        atomicAdd(p1 + 0, acc[mf][nf][2]);
                        atomicAdd(p1 + 1, acc[mf][nf][3]);
                    } else {
                        p0[0] = acc[mf][nf][0]; p0[1] = acc[mf][nf][1];
                        p1[0] = acc[mf][nf][2]; p1[1] = acc[mf][nf][3];
                    }
                }
            } else if (mode == 1) {
                const int d = n % DQK_;
#pragma unroll
                for (int rr = 0; rr < 2; rr++) {
                    const int mr = m + rr * 8;
                    float x1 = acc[mf][nf][rr * 2 + 0] * qscale;
                    float x2 = acc[mf][nf][rr * 2 + 1] * qscale;
                    if (d >= DN_) {
                        const int j = (d - DN_) >> 1;
                        const float cc = g_cos[mr * 32 + j], ss = g_sin[mr * 32 + j];
                        const float o1 = x1 * cc - x2 * ss, o2 = x2 * cc + x1 * ss;
                        x1 = o1; x2 = o2;
                    }
                    *(uint32_t*)(outH + (size_t)mr * ldC + n) =
                        pack2h(__float2half_rn(x1), __float2half_rn(x2));
                }
            } else { // mode 2
                const int d = n & 255, hh = n >> 8;
#pragma unroll
                for (int rr = 0; rr < 2; rr++) {
                    const int mr = m + rr * 8;
                    const float x1 = acc[mf][nf][rr * 2 + 0];
                    const float x2 = acc[mf][nf][rr * 2 + 1];
                    if (d < DN_) {
                        *(uint32_t*)(outH + ((size_t)mr * NH_ + hh) * DQK_ + d) =
                            pack2h(__float2half_rn(x1), __float2half_rn(x2));
                    } else {
                        *(uint32_t*)(voutH + ((size_t)mr * NH_ + hh) * DV_ + (d - DN_)) =
                            pack2h(__float2half_rn(x1), __float2half_rn(x2));
                    }
                }
            }
        }
    }
}

// mode-0 GEMM with split-K via gridDim.z; z-pairs route to distinct buffers
// (2 commutative atomic addends per buffer -> deterministic).
__global__ void __launch_bounds__(256, 2)
gemm_hmma(const __half* __restrict__ A, const __half* __restrict__ Bw,
          float* __restrict__ C, int Nreal, int ldC, int K, int ldB) {
    extern __shared__ char smem[];
    const int nsplit = gridDim.z;
    const int Kpart = K / nsplit;
    const int kbase = blockIdx.z * Kpart;
    float* Ct = C;
    const int g = blockIdx.z >> 1;
    if (g > 0) Ct = &g_part[g - 1][0];
    gemm_body(A, Bw, Ct, Nreal, ldC, K, ldB, 0, nullptr, nullptr,
              blockIdx.y * 128, blockIdx.x * 128, kbase, Kpart,
              nsplit > 1 ? 1 : 0, smem);
}

// fused GEMM2 (mode 1) + GEMM3 (mode 2) in one grid; GEMM2 tiles first.
#define G2_CTAS (((NH_*DQK_) / 128) * (T_ / 128))   // 192*8 = 1536
#define G3_CTAS (((NH_*DKV_) / 128) * (T_ / 128))   // 256*8 = 2048
__global__ void __launch_bounds__(256, 2)
gemm23_fused() {
    extern __shared__ char smem[];
    int id = blockIdx.x;
    const __half* A; const __half* Bw; __half* oH; __half* vH;
    int mode, Nn, K, bm, bn;
    if (id < G2_CTAS) {
        const int bx = id % ((NH_*DQK_) / 128), by = id / ((NH_*DQK_) / 128);
        A = g_qan; Bw = g_w2; oH = g_qh; vH = nullptr;
        mode = 1; Nn = NH_ * DQK_; K = QLR_;
        bm = by * 128; bn = bx * 128;
    } else {
        id -= G2_CTAS;
        const int bx = id % ((NH_*DKV_) / 128), by = id / ((NH_*DKV_) / 128);
        A = g_kvan; Bw = g_w3; oH = g_kh; vH = g_vh;
        mode = 2; Nn = NH_ * DKV_; K = KVLR_;
        bm = by * 128; bn = bx * 128;
    }
    gemm_body(A, Bw, nullptr, Nn, Nn, K, Nn, mode, oH, vH,
              bm, bn, 0, K, 0, smem);
}

// ======================= rmsnorm (both in one launch) ========================
__global__ void rmsnorm2_kernel(const float* __restrict__ qw,
                                const float* __restrict__ kvw) {
    const int row = blockIdx.x;
    const int which = blockIdx.y;
    const int W = which ? KVLR_ : QLR_;
    const int off = which ? QLR_ : 0;
    const float* w = which ? kvw : qw;
    __half* H = which ? g_kvan : g_qan;
    const float* xr = g_qkv + (size_t)row * NQKV_ + off;
    float ss = 0.f;
    for (int c = threadIdx.x; c < W; c += blockDim.x) {
        float v = xr[c];
        ss += v * v;
    }
    __shared__ float red[32];
#pragma unroll
    for (int o = 16; o; o >>= 1) ss += __shfl_xor_sync(0xffffffffu, ss, o);
    if ((threadIdx.x & 31) == 0) red[threadIdx.x >> 5] = ss;
    __syncthreads();
    if (threadIdx.x < 32) {
        float v = (threadIdx.x < (blockDim.x >> 5)) ? red[threadIdx.x] : 0.f;
#pragma unroll
        for (int o = 16; o; o >>= 1) v += __shfl_xor_sync(0xffffffffu, v, o);
        red[threadIdx.x] = v;
    }
    __syncthreads();
    const float rstd = rsqrtf(red[0] / (float)W + 1e-6f);
    for (int c = threadIdx.x; c < W; c += blockDim.x)
        H[(size_t)row * W + c] = __float2half_rn(xr[c] * rstd * w[c]);
}

// ======================= RoPE tables + k_pe broadcast ========================
__global__ void rope_tab_kernel(const int* __restrict__ pos) {
    const int t = blockIdx.x, i = threadIdx.x;
    double inv = pow(10000.0, -(double)i / 32.0);
    double f = (double)pos[t] * inv;
    double s, c;
    sincos(f, &s, &c);
    g_cos[t * 32 + i] = (float)c;
    g_sin[t * 32 + i] = (float)s;
}

__global__ void kpe_build_kernel() {
    const int t = blockIdx.x;
    const int i = threadIdx.x;
    const int hh = threadIdx.y;
    const float c = g_cos[t * 32 + i];
    const float s = g_sin[t * 32 + i];
    const float* src = g_qkv + (size_t)t * NQKV_ + (QLR_ + KVLR_) + 2 * i;
    const float x1 = src[0], x2 = src[1];
    const uint32_t hv = pack2h(__float2half_rn(x1 * c - x2 * s),
                               __float2half_rn(x2 * c + x1 * s));
    for (int h = hh; h < NH_; h += 8)
        *(uint32_t*)(g_kh + ((size_t)t * NH_ + h) * DQK_ + DN_ + 2 * i) = hv;
}

// ======================= fp16 HMMA flash attention ===========================
#define QKP 200
#define VPITCH 272
#define PVP 72
#define SFP 68

struct ASmem {
    __half Q[64 * QKP];
    __half K[64 * QKP];
    char  V[64 * VPITCH];
    __half P[64 * PVP];
    float Sf[64 * SFP];
    float rowM[64], rowL[64], rowScale[64];
};
#define ATTN_SMEM sizeof(ASmem)

__global__ void __launch_bounds__(256, 2)
attn_mma() {
    extern __shared__ char smem_raw[];
    ASmem& sm = *(ASmem*)smem_raw;
    const int h = blockIdx.x;
    const int qb = (int)gridDim.y - 1 - (int)blockIdx.y;  // long tiles first
    const int tid = threadIdx.x, wid = tid >> 5, lane = tid & 31;
    const int wm = wid & 3, wn = wid >> 2;
    const int t0 = qb * 64;
    const int lm = lane >> 2, ln = (lane & 3) * 2;

    const uint32_t sQ = smem_u32(sm.Q);
    const uint32_t sK = smem_u32(sm.K);
    const uint32_t sV = smem_u32(sm.V);
    const uint32_t sP = smem_u32(sm.P);

    auto loadK = [&](int kc) {
        const int tk0 = kc * 64;
        for (int idx = tid; idx < 64 * 24; idx += 256) {
            const int row = idx / 24, ch = idx % 24;
            CP_ASYNC16(sK + (row * QKP + ch * 8) * 2,
                       g_kh + ((size_t)(tk0 + row) * NH_ + h) * DQK_ + ch * 8);
        }
    };
    auto loadV = [&](int kc) {
        const int tk0 = kc * 64;
        for (int idx = tid; idx < 64 * 16; idx += 256) {
            const int row = idx >> 4, ch = idx & 15;
            CP_ASYNC16(sV + row * VPITCH + ch * 16,
                       g_vh + ((size_t)(tk0 + row) * NH_ + h) * DV_ + ch * 8);
        }
    };

    for (int idx = tid; idx < 64 * 24; idx += 256) {
        const int row = idx / 24, ch = idx % 24;
        CP_ASYNC16(sQ + (row * QKP + ch * 8) * 2,
                   g_qh + ((size_t)(t0 + row) * NH_ + h) * DQK_ + ch * 8);
    }
    CP_COMMIT();
    loadK(0); CP_COMMIT();
    loadV(0); CP_COMMIT();

    if (tid < 64) {
        sm.rowM[tid] = -1e30f;
        sm.rowL[tid] = 0.f;
    }

    const uint32_t aoffQ = ((wm * 16 + (lane & 15)) * QKP + ((lane >> 4) & 1) * 8) * 2;
    uint32_t boffK[4];
#pragma unroll
    for (int nf = 0; nf < 4; nf++)
        boffK[nf] = ((wn * 32 + nf * 8 + (lane & 7)) * QKP + ((lane >> 3) & 1) * 8) * 2;
    const uint32_t aoffP = ((wm * 16 + (lane & 15)) * PVP + ((lane >> 4) & 1) * 8) * 2;
    uint32_t voffT[4];
#pragma unroll
    for (int j = 0; j < 4; j++)
        voffT[j] = (lane & 15) * VPITCH + (wn * 64 + j * 16 + ((lane >> 4) & 1) * 8) * 2;

    float accO[8][4];
#pragma unroll
    for (int i = 0; i < 8; i++)
#pragma unroll
        for (int q = 0; q < 4; q++) accO[i][q] = 0.f;

    for (int kc = 0; kc <= qb; kc++) {
        const int tk0 = kc * 64;
        CP_WAIT1();
        __syncthreads();

        float accS[4][4];
#pragma unroll
        for (int i = 0; i < 4; i++)
#pragma unroll
            for (int q = 0; q < 4; q++) accS[i][q] = 0.f;
#pragma unroll
        for (int ks = 0; ks < 12; ks++) {
            uint32_t a[4];
            LDSM_X4(a[0], a[1], a[2], a[3], sQ + aoffQ + ks * 32);
#pragma unroll
            for (int nf = 0; nf < 4; nf++) {
                uint32_t b[2];
                LDSM_X2(b[0], b[1], sK + boffK[nf] + ks * 32);
                MMA16816(accS[nf], a, b);
            }
        }
        const bool diag = (kc == qb);
#pragma unroll
        for (int nf = 0; nf < 4; nf++) {
            const int r = wm * 16 + lm;
            const int c = wn * 32 + nf * 8 + ln;
            float v0 = accS[nf][0], v1 = accS[nf][1], v2 = accS[nf][2], v3 = accS[nf][3];
            if (diag) {
                const int rg0 = t0 + r, rg1 = rg0 + 8, cg = tk0 + c;
                if (cg > rg0) v0 = -1e30f;
                if (cg + 1 > rg0) v1 = -1e30f;
                if (cg > rg1) v2 = -1e30f;
                if (cg + 1 > rg1) v3 = -1e30f;
            }
            sm.Sf[r * SFP + c] = v0;
            sm.Sf[r * SFP + c + 1] = v1;
            sm.Sf[(r + 8) * SFP + c] = v2;
            sm.Sf[(r + 8) * SFP + c + 1] = v3;
        }
        __syncthreads();

        if (kc < qb) { loadK(kc + 1); CP_COMMIT(); }

        {
            const int row = tid >> 2, l4 = tid & 3;
            float mloc = -1e30f;
#pragma unroll
            for (int c = 0; c < 16; c++) mloc = fmaxf(mloc, sm.Sf[row * SFP + l4 * 16 + c]);
            mloc = fmaxf(mloc, __shfl_xor_sync(0xffffffffu, mloc, 1));
            mloc = fmaxf(mloc, __shfl_xor_sync(0xffffffffu, mloc, 2));
            const float mprev = sm.rowM[row];
            const float mnew = fmaxf(mprev, mloc);
            float lsum = 0.f;
#pragma unroll
            for (int c = 0; c < 16; c += 2) {
                const int col = l4 * 16 + c;
                const float p0 = __expf(sm.Sf[row * SFP + col] - mnew);
                const float p1 = __expf(sm.Sf[row * SFP + col + 1] - mnew);
                lsum += p0 + p1;
                *(uint32_t*)(sm.P + row * PVP + col) =
                    pack2h(__float2half_rn(p0), __float2half_rn(p1));
            }
            lsum += __shfl_xor_sync(0xffffffffu, lsum, 1);
            lsum += __shfl_xor_sync(0xffffffffu, lsum, 2);
            if (l4 == 0) {
                const float sc = __expf(mprev - mnew);
                sm.rowScale[row] = sc;
                sm.rowM[row] = mnew;
                sm.rowL[row] = sm.rowL[row] * sc + lsum;
            }
        }

        if (kc < qb) { CP_WAIT1(); } else { CP_WAIT0(); }
        __syncthreads();

        const float s0 = sm.rowScale[wm * 16 + lm];
        const float s1 = sm.rowScale[wm * 16 + lm + 8];
#pragma unroll
        for (int nf = 0; nf < 8; nf++) {
            accO[nf][0] *= s0; accO[nf][1] *= s0;
            accO[nf][2] *= s1; accO[nf][3] *= s1;
        }
#pragma unroll
        for (int ks = 0; ks < 4; ks++) {
            uint32_t pa[4];
            LDSM_X4(pa[0], pa[1], pa[2], pa[3], sP + aoffP + ks * 32);
#pragma unroll
            for (int j = 0; j < 4; j++) {
                uint32_t vb[4];
                LDSM_X4T(vb[0], vb[1], vb[2], vb[3],
                         sV + voffT[j] + ks * (16 * VPITCH));
                MMA16816(accO[2*j],     pa, vb);
                MMA16816(accO[2*j + 1], pa, vb + 2);
            }
        }
        __syncthreads();

        if (kc < qb) { loadV(kc + 1); CP_COMMIT(); }
    }

    const float invL0 = 1.f / sm.rowL[wm * 16 + lm];
    const float invL1 = 1.f / sm.rowL[wm * 16 + lm + 8];
    const int r0g = t0 + wm * 16 + lm;
#pragma unroll
    for (int nf = 0; nf < 8; nf++) {
        const int col = h * DV_ + wn * 64 + nf * 8 + ln;
        *(uint32_t*)(g_a + (size_t)r0g * (NH_ * DV_) + col) =
            pack2h(__float2half_rn(accO[nf][0] * invL0), __float2half_rn(accO[nf][1] * invL0));
        *(uint32_t*)(g_a + (size_t)(r0g + 8) * (NH_ * DV_) + col) =
            pack2h(__float2half_rn(accO[nf][2] * invL1), __float2half_rn(accO[nf][3] * invL1));
    }
}

// ======================= launch ==============================================
extern "C" void kernel_launch(void* const* d_in, const int* in_sizes, int n_in,
                              void* d_out, int out_size) {
    const int*   positions = (const int*)d_in[0];
    const float* hidden    = (const float*)d_in[1];
    const float* w_qkv_a   = (const float*)d_in[2];
    const float* q_a_ln_w  = (const float*)d_in[3];
    const float* w_q_b     = (const float*)d_in[4];
    const float* kv_a_ln_w = (const float*)d_in[5];
    const float* w_kv_b    = (const float*)d_in[6];
    const float* w_o       = (const float*)d_in[7];
    float* out = (float*)d_out;

    float* p_qkv;
    cudaGetSymbolAddress((void**)&p_qkv, g_qkv);

    __half *w1, *w2, *w3, *w4, *a;
    cudaGetSymbolAddress((void**)&w1, g_w1);
    cudaGetSymbolAddress((void**)&w2, g_w2);
    cudaGetSymbolAddress((void**)&w3, g_w3);
    cudaGetSymbolAddress((void**)&w4, g_w4);
    cudaGetSymbolAddress((void**)&a,  g_a);

    cudaFuncSetAttribute(gemm_hmma, cudaFuncAttributeMaxDynamicSharedMemorySize, GEMM_SMEM);
    cudaFuncSetAttribute(gemm23_fused, cudaFuncAttributeMaxDynamicSharedMemorySize, GEMM_SMEM);
    cudaFuncSetAttribute(attn_mma, cudaFuncAttributeMaxDynamicSharedMemorySize, (int)ATTN_SMEM);

    // keep gemm_hmma (GEMM1) as the 4th launch for ncu capture
    zero_qkv_kernel<<<(T_ * NQKV_ / 4 + 255) / 256, 256>>>();
    {
        int t8 = HID_ * NQKV_PAD_ / 8;
        convHpad_kernel<<<(t8 + 255) / 256, 256>>>(w_qkv_a, w1, NQKV_, NQKV_PAD_, t8);
    }
    convA8_kernel<<<(T_ * HID_ / 8 + 255) / 256, 256>>>(hidden, a, T_ * HID_ / 8);
    // GEMM1 split-K=2 (both z into g_qkv; 2 commutative addends)
    gemm_hmma<<<dim3(NQKV_PAD_ / 128, T_ / 128, 2), 256, GEMM_SMEM>>>(
        a, w1, p_qkv, NQKV_, NQKV_, HID_, NQKV_PAD_);

    {
        int t16;
        t16 = QLR_ * (NH_ * DQK_) / 16;
        convH16_kernel<<<(t16 + 255) / 256, 256>>>(w_q_b, w2, t16);
        t16 = KVLR_ * (NH_ * DKV_) / 16;
        convH16_kernel<<<(t16 + 255) / 256, 256>>>(w_kv_b, w3, t16);
        t16 = (NH_ * DV_) * HID_ / 16;
        convH16_kernel<<<(t16 + 255) / 256, 256>>>(w_o, w4, t16);
    }

    // zero d_out + 3 partial buffers (GEMM4 split-K=8 targets)
    zero_out4_kernel<<<(T_ * HID_ / 4 + 255) / 256, 256>>>(out, T_ * HID_ / 4);

    rope_tab_kernel<<<T_, 32>>>(positions);
    rmsnorm2_kernel<<<dim3(T_, 2), 256>>>(q_a_ln_w, kv_a_ln_w);

    // fused GEMM2+GEMM3 (one grid, GEMM2 tiles first)
    gemm23_fused<<<G2_CTAS + G3_CTAS, 256, GEMM_SMEM>>>();

    kpe_build_kernel<<<T_, dim3(32, 8)>>>();

    attn_mma<<<dim3(NH_, T_ / 64), 256, ATTN_SMEM>>>();

    // GEMM4 split-K=8: z-pairs -> {out, part0, part1, part2}, 2 addends each
    gemm_hmma<<<dim3(HID_ / 128, T_ / 128, 8), 256, GEMM_SMEM>>>(
        a, w4, out, HID_, HID_, NH_ * DV_, HID_);
    addpart3_kernel<<<(T_ * HID_ / 4 + 255) / 256, 256>>>(out, T_ * HID_ / 4);
}